// round 14
// baseline (speedup 1.0000x reference)
#include <cuda_runtime.h>
#include <cstdint>

// ---------------------------------------------------------------------------
// out = ((x @ (w1_q*s1)) @ (w2_q*s2)) per expert.  E=8, T=4096, H=2048.
// Exact 16-bit activation split (hi,lo int8 planes).
// L1-AS-TILE-BUFFER GEMM (R13 fixed: full-size weight buffers + convergent
// barrier): no smem staging, no pipeline. Operands pre-laid-out in gmem in
// FRAGMENT ORDER (IMMA) / ROW-MAJOR (dp4a); every warp streams its own
// k-loop; L1 caches the ~40KB/CTA working set; CTAs share tiles via L2.
//   warps 0-3: hi plane IMMA (64x32 tiles)   warps 4-7: lo plane DP4A (32x64)
// out = (256*acc_hi + acc_lo) * s_row * wscale_col.
// ---------------------------------------------------------------------------

#define EE 8
#define TT 4096
#define HH 2048

#define BM 128
#define BN 64
#define NKIT 16                 // k-iterations of 128
#define XPITCH 68               // padded pitch for lo-acc exchange
#define DYNSMEM (128 * XPITCH * 4)   // 34816 B -> 2 CTAs/SM

// -------------------- scratch ----------------------------------------------
// B weights per layer, two layouts, tiles of 64(n)x128(k), 8KB each:
//   frag:  [e][nb32][kb16][ (nblk*4+ks)*256 + lane*8 + reg*4 ]
//   row :  [e][nb32][kb16][ n*128 + kk ]
// A activations, tiles of 128(m)x128(k), 16KB each:
//   hi frag: [e][mb32][kb16][ wm*8192 + (mt*4+ks)*512 + lane*16 + reg*4 ]
//   lo row : [e][mb32][kb16][ r*128 + kk ]
__device__ int8_t g_w1f[(size_t)EE * HH * HH];
__device__ int8_t g_w1r[(size_t)EE * HH * HH];
__device__ int8_t g_w2f[(size_t)EE * HH * HH];
__device__ int8_t g_w2r[(size_t)EE * HH * HH];
__device__ int8_t g_ahf[(size_t)EE * TT * HH];
__device__ int8_t g_alr[(size_t)EE * TT * HH];
__device__ float  g_rs [(size_t)EE * TT];
__device__ float  g_h  [(size_t)EE * TT * HH];   // layer-1 output fp32

// -------------------- helpers --------------------------------------------
__device__ __forceinline__ void imma(int* d, const uint32_t* a,
                                     const uint32_t* b) {
    asm volatile(
        "mma.sync.aligned.m16n8k32.row.col.s32.s8.s8.s32 "
        "{%0,%1,%2,%3},{%4,%5,%6,%7},{%8,%9},{%0,%1,%2,%3};"
        : "+r"(d[0]), "+r"(d[1]), "+r"(d[2]), "+r"(d[3])
        : "r"(a[0]), "r"(a[1]), "r"(a[2]), "r"(a[3]),
          "r"(b[0]), "r"(b[1]));
}

__device__ __forceinline__ int dp4a_(int a, int b, int c) {
    int d;
    asm("dp4a.s32.s32 %0, %1, %2, %3;" : "=r"(d) : "r"(a), "r"(b), "r"(c));
    return d;
}

// -------------------- weight convert: int32 [E][k][n] -> frag + row --------
__global__ void convw_kernel(const int* __restrict__ W,
                             int8_t* __restrict__ Ofrag,
                             int8_t* __restrict__ Orow) {
    __shared__ int8_t tile[32][33];
    const int e  = blockIdx.z;
    const int n0 = blockIdx.x * 32;
    const int k0 = blockIdx.y * 32;
    const int tx = threadIdx.x, ty = threadIdx.y;

    const int* src = W + ((size_t)e * HH + k0) * HH + n0;
#pragma unroll
    for (int r = 0; r < 4; r++) {
        tile[ty + r * 8][tx] = (int8_t)src[(size_t)(ty + r * 8) * HH + tx];
    }
    __syncthreads();
    const int t  = ty * 32 + tx;
    const int nr = t >> 3;              // 0..31 (n within block)
    const int c4 = (t & 7) * 4;         // 0..28 (k within block)
    uint32_t p = (uint32_t)(uint8_t)tile[c4 + 0][nr]
               | ((uint32_t)(uint8_t)tile[c4 + 1][nr] << 8)
               | ((uint32_t)(uint8_t)tile[c4 + 2][nr] << 16)
               | ((uint32_t)(uint8_t)tile[c4 + 3][nr] << 24);
    const int ng   = n0 + nr;
    const int nb   = ng >> 6;
    const int rowT = ng & 63;
    const int kb   = k0 >> 7;
    const int kin  = (k0 & 127) + c4;
    const size_t tbase = (((size_t)(e * 32 + nb) * 16 + kb) << 13);
    // row-major
    *(uint32_t*)(Orow + tbase + rowT * 128 + kin) = p;
    // fragment order
    const int nblk = rowT >> 3, grp = rowT & 7;
    const int ks = kin >> 5, c = (kin >> 4) & 1, tg = (kin >> 2) & 3;
    *(uint32_t*)(Ofrag + tbase + (nblk * 4 + ks) * 256
                 + (grp * 4 + tg) * 8 + c * 4) = p;
}

// -------------------- activation quantize: hi frag + lo row ---------------
__global__ void quant_kernel(const float* __restrict__ X,
                             int8_t* __restrict__ Qh,
                             int8_t* __restrict__ Ql,
                             float* __restrict__ RS) {
    const int row = blockIdx.x;          // 0 .. EE*TT-1
    const float* x = X + (size_t)row * HH;
    const int t = threadIdx.x;           // 0..127

    float4 v[4];
#pragma unroll
    for (int j = 0; j < 4; j++) v[j] = ((const float4*)x)[t * 4 + j];

    float m = 0.0f;
#pragma unroll
    for (int j = 0; j < 4; j++) {
        m = fmaxf(m, fabsf(v[j].x)); m = fmaxf(m, fabsf(v[j].y));
        m = fmaxf(m, fabsf(v[j].z)); m = fmaxf(m, fabsf(v[j].w));
    }
#pragma unroll
    for (int o = 16; o; o >>= 1)
        m = fmaxf(m, __shfl_xor_sync(0xFFFFFFFFu, m, o));
    __shared__ float wr[4];
    if ((t & 31) == 0) wr[t >> 5] = m;
    __syncthreads();
    float mx = fmaxf(fmaxf(wr[0], wr[1]), fmaxf(wr[2], wr[3]));
    mx = fmaxf(mx, 1e-20f);
    const float inv = 32600.0f / mx;

    uint32_t hw[4], lw[4];
#pragma unroll
    for (int j = 0; j < 4; j++) {
        const int q0 = __float2int_rn(v[j].x * inv);
        const int q1 = __float2int_rn(v[j].y * inv);
        const int q2 = __float2int_rn(v[j].z * inv);
        const int q3 = __float2int_rn(v[j].w * inv);
        const int h0 = (q0 + 128) >> 8, h1 = (q1 + 128) >> 8;
        const int h2 = (q2 + 128) >> 8, h3 = (q3 + 128) >> 8;
        const int l0 = q0 - (h0 << 8), l1 = q1 - (h1 << 8);
        const int l2 = q2 - (h2 << 8), l3 = q3 - (h3 << 8);
        hw[j] = (h0 & 255) | ((h1 & 255) << 8) | ((h2 & 255) << 16)
              | ((uint32_t)(h3 & 255) << 24);
        lw[j] = (l0 & 255) | ((l1 & 255) << 8) | ((l2 & 255) << 16)
              | ((uint32_t)(l3 & 255) << 24);
    }

    const int e   = row >> 12;
    const int mm  = row & 4095;
    const int mb  = mm >> 7;
    const int r   = mm & 127;
    const int kb  = t >> 3;
    const int sub = t & 7;
    const size_t tbase = (((size_t)(e * 32 + mb) * 16 + kb) << 14);

    // lo: row-major 16B store
    *(int4*)(Ql + tbase + r * 128 + sub * 16) =
        make_int4(lw[0], lw[1], lw[2], lw[3]);

    // hi: fragment-order 4B stores
    const int wm = r >> 6, mt = (r >> 4) & 3, h = (r >> 3) & 1, grp = r & 7;
    const int ks = sub >> 1, c = sub & 1;
    const size_t hb = tbase + wm * 8192 + (mt * 4 + ks) * 512;
#pragma unroll
    for (int j = 0; j < 4; j++) {
        *(uint32_t*)(Qh + hb + (grp * 4 + j) * 16 + (c * 2 + h) * 4) = hw[j];
    }
    if (t == 0) RS[row] = mx / 32600.0f;
}

// -------------------- barrier-free L1-streaming GEMM -----------------------
__global__ void __launch_bounds__(256, 2)
imma_gemm(const int8_t* __restrict__ Ahf, const int8_t* __restrict__ Alr,
          const float* __restrict__ rs,
          const int8_t* __restrict__ Bf, const int8_t* __restrict__ Br,
          const float* __restrict__ cs, float* __restrict__ C) {
    extern __shared__ __align__(16) char sm[];
    const int tid = threadIdx.x;
    const int lane = tid & 31, wid = tid >> 5;

    const int e  = blockIdx.z;
    const int mb = blockIdx.y;           // 0..31
    const int nb = blockIdx.x;           // 0..31

    const int8_t* Ahb = Ahf + (((size_t)(e * 32 + mb) * 16) << 14);
    const int8_t* Alb = Alr + (((size_t)(e * 32 + mb) * 16) << 14);
    const int8_t* Bfb = Bf  + (((size_t)(e * 32 + nb) * 16) << 13);
    const int8_t* Brb = Br  + (((size_t)(e * 32 + nb) * 16) << 13);

    int* xch = (int*)sm;                 // 128 x XPITCH int32

    // role configs
    const int grp = lane >> 2;
    const int wm = (wid & 3) >> 1;       // imma: 0..1 -> 64 rows
    const int wn = wid & 1;              // imma: 0..1 -> 32 cols
    const int wtr = wid - 4;             // dp4a: 0..3 -> rows wtr*32
    const int lg = lane & 3;
    const int lh = lane >> 2;

    int acc_h[4][4][4];                  // imma accs (warps 0-3)
    int acc_d[8][8];                     // dp4a accs (warps 4-7)

    if (wid < 4) {
        // ================= IMMA warps: hi plane =================
        const int8_t* ab = Ahb + wm * 8192;
        const int8_t* bb = Bfb + wn * 4096;
#pragma unroll
        for (int a = 0; a < 4; a++)
#pragma unroll
            for (int b = 0; b < 4; b++)
#pragma unroll
                for (int c = 0; c < 4; c++) acc_h[a][b][c] = 0;

#pragma unroll 1
        for (int i = 0; i < NKIT; i++) {
            const int8_t* at = ab + ((size_t)i << 14);
            const int8_t* bt = bb + ((size_t)i << 13);
#pragma unroll
            for (int ks = 0; ks < 4; ks++) {
                int4 af[4];
#pragma unroll
                for (int mt = 0; mt < 4; mt++)
                    af[mt] = *(const int4*)(at + (mt * 4 + ks) * 512
                                            + lane * 16);
                int2 bfr[4];
#pragma unroll
                for (int nt = 0; nt < 4; nt++)
                    bfr[nt] = *(const int2*)(bt + (nt * 4 + ks) * 256
                                             + lane * 8);
#pragma unroll
                for (int mt = 0; mt < 4; mt++)
#pragma unroll
                    for (int nt = 0; nt < 4; nt++)
                        imma(acc_h[mt][nt], (const uint32_t*)&af[mt],
                             (const uint32_t*)&bfr[nt]);
            }
        }
    } else {
        // ================= dp4a warps: lo plane =================
        const int8_t* arow = Alb + (wtr * 32 + lg) * 128;
        const int8_t* brow = Brb + lh * 128;
#pragma unroll
        for (int a = 0; a < 8; a++)
#pragma unroll
            for (int b = 0; b < 8; b++) acc_d[a][b] = 0;

#pragma unroll 1
        for (int i = 0; i < NKIT; i++) {
            const int8_t* at = arow + ((size_t)i << 14);
            const int8_t* bt = brow + ((size_t)i << 13);
#pragma unroll 2
            for (int kb = 0; kb < 8; kb++) {
                int4 bv[8];
#pragma unroll
                for (int j2 = 0; j2 < 8; j2++)
                    bv[j2] = *(const int4*)(bt + j2 * 1024 + kb * 16);
#pragma unroll
                for (int j = 0; j < 8; j++) {
                    const int4 a = *(const int4*)(at + j * 512 + kb * 16);
#pragma unroll
                    for (int j2 = 0; j2 < 8; j2++) {
                        acc_d[j][j2] =
                            dp4a_(a.x, bv[j2].x,
                            dp4a_(a.y, bv[j2].y,
                            dp4a_(a.z, bv[j2].z,
                            dp4a_(a.w, bv[j2].w, acc_d[j][j2]))));
                    }
                }
            }
        }
        // stage lo accs into smem for the IMMA warps' epilogue
#pragma unroll
        for (int j = 0; j < 8; j++)
#pragma unroll
            for (int j2 = 0; j2 < 8; j2++) {
                const int r = wtr * 32 + lg + 4 * j;
                const int c = lh + 8 * j2;
                xch[r * XPITCH + c] = acc_d[j][j2];
            }
    }

    __syncthreads();   // single convergent barrier

    if (wid < 4) {
        const float* rsp = rs + (size_t)e * TT + mb * BM;
        const float* csp = cs + (size_t)e * HH + nb * BN;
        float* Cg = C + ((size_t)e * TT + mb * BM) * HH + nb * BN;

#pragma unroll
        for (int mt = 0; mt < 4; mt++) {
            const int rA = wm * 64 + mt * 16 + grp;
            const float sr0 = rsp[rA];
            const float sr1 = rsp[rA + 8];
#pragma unroll
            for (int nt = 0; nt < 4; nt++) {
                const int cn = wn * 32 + nt * 8 + (lane & 3) * 2;
                const float sc0 = csp[cn];
                const float sc1 = csp[cn + 1];
                const int* hh = acc_h[mt][nt];
                const int2 l0 = *(const int2*)(xch + rA * XPITCH + cn);
                const int2 l1 = *(const int2*)(xch + (rA + 8) * XPITCH + cn);
                float2 r0, r1;
                r0.x = fmaf(256.0f, (float)hh[0], (float)l0.x) * (sr0 * sc0);
                r0.y = fmaf(256.0f, (float)hh[1], (float)l0.y) * (sr0 * sc1);
                r1.x = fmaf(256.0f, (float)hh[2], (float)l1.x) * (sr1 * sc0);
                r1.y = fmaf(256.0f, (float)hh[3], (float)l1.y) * (sr1 * sc1);
                *(float2*)(Cg + (size_t)rA * HH + cn)       = r0;
                *(float2*)(Cg + (size_t)(rA + 8) * HH + cn) = r1;
            }
        }
    }
}

// -------------------- launcher --------------------------------------------
extern "C" void kernel_launch(void* const* d_in, const int* in_sizes, int n_in,
                              void* d_out, int out_size) {
    const float* x   = (const float*)d_in[0];
    const int*   w1q = (const int*)d_in[1];
    const float* w1s = (const float*)d_in[2];
    const int*   w2q = (const int*)d_in[3];
    const float* w2s = (const float*)d_in[4];
    float*       out = (float*)d_out;

    void *pw1f, *pw1r, *pw2f, *pw2r, *pahf, *palr, *prs, *ph;
    cudaGetSymbolAddress(&pw1f, g_w1f);
    cudaGetSymbolAddress(&pw1r, g_w1r);
    cudaGetSymbolAddress(&pw2f, g_w2f);
    cudaGetSymbolAddress(&pw2r, g_w2r);
    cudaGetSymbolAddress(&pahf, g_ahf);
    cudaGetSymbolAddress(&palr, g_alr);
    cudaGetSymbolAddress(&prs,  g_rs);
    cudaGetSymbolAddress(&ph,   g_h);

    dim3 cb(32, 8), cg(HH / 32, HH / 32, EE);
    convw_kernel<<<cg, cb>>>(w1q, (int8_t*)pw1f, (int8_t*)pw1r);
    convw_kernel<<<cg, cb>>>(w2q, (int8_t*)pw2f, (int8_t*)pw2r);

    quant_kernel<<<EE * TT, 128>>>(x, (int8_t*)pahf, (int8_t*)palr,
                                   (float*)prs);

    cudaFuncSetAttribute(imma_gemm,
                         cudaFuncAttributeMaxDynamicSharedMemorySize, DYNSMEM);
    dim3 gg(HH / BN, TT / BM, EE);   // (32, 32, 8)

    imma_gemm<<<gg, 256, DYNSMEM>>>((const int8_t*)pahf, (const int8_t*)palr,
                                    (const float*)prs, (const int8_t*)pw1f,
                                    (const int8_t*)pw1r, w1s, (float*)ph);

    quant_kernel<<<EE * TT, 128>>>((const float*)ph, (int8_t*)pahf,
                                   (int8_t*)palr, (float*)prs);

    imma_gemm<<<gg, 256, DYNSMEM>>>((const int8_t*)pahf, (const int8_t*)palr,
                                    (const float*)prs, (const int8_t*)pw2f,
                                    (const int8_t*)pw2r, w2s, out);
}

// round 15
// speedup vs baseline: 1.2411x; 1.2411x over previous
#include <cuda_runtime.h>
#include <cstdint>

// ---------------------------------------------------------------------------
// out = ((x @ (w1_q*s1)) @ (w2_q*s2)) per expert.  E=8, T=4096, H=2048.
// Exact 16-bit activation split (hi,lo int8 planes).
// R12 decoupled smem pipeline (2 CTAs/SM, mbarrier full/free, bulk-copy)
// + FRAGMENT-ORDER smem tiles for the IMMA side: A-hi & B-frag stored in
// mma fragment order so IMMA warps use 8 wide LDS per ks (vs 24 LDS.32).
// dp4a side keeps the proven chunk-swizzled layout.
//   warps 0-3: hi plane IMMA (64x32 tiles)   warps 4-7: lo plane DP4A (32x64)
// out = (256*acc_hi + acc_lo) * s_row * wscale_col.
// ---------------------------------------------------------------------------

#define EE 8
#define TT 4096
#define HH 2048

#define BM 128
#define BN 64
#define NKIT 16                 // k-iterations of 128
#define OFF_ALO 16384
#define OFF_BF  32768
#define OFF_BS  40960
#define STAGE   49152           // AhiF 16K + AloS 16K + Bfrag 8K + Bswz 8K
#define NSTAGE 2
#define DYNSMEM (NSTAGE * STAGE)     // 98304 -> 2 CTAs/SM
#define XPITCH 68               // padded pitch for lo-acc exchange

// -------------------- scratch ----------------------------------------------
// weights per layer (full size each; two layouts), tiles 64(n)x128(k) = 8KB:
//   frag: [e][nb32][kb16][(nblk*4+ks)*256 + lane*8 + c*4]
//   swz : [e][nb32][kb16][n*128 + ((ch^(n&7))&7)<<4 + (kk&15)]
// activations, tiles 128(m)x128(k) = 16KB:
//   hi frag: [e][mb32][kb16][wm*8192 + (mt*4+ks)*512 + lane*16 + r4]
//   lo swz : [e][mb32][kb16][r*128 + ((ch^(r&7))&7)<<4 + (kk&15)]
__device__ int8_t g_w1f[(size_t)EE * HH * HH];
__device__ int8_t g_w1s[(size_t)EE * HH * HH];
__device__ int8_t g_w2f[(size_t)EE * HH * HH];
__device__ int8_t g_w2s[(size_t)EE * HH * HH];
__device__ int8_t g_ahf[(size_t)EE * TT * HH];
__device__ int8_t g_als[(size_t)EE * TT * HH];
__device__ float  g_rs [(size_t)EE * TT];
__device__ float  g_h  [(size_t)EE * TT * HH];   // layer-1 output fp32

// -------------------- helpers --------------------------------------------
__device__ __forceinline__ uint32_t smem_u32(const void* p) {
    uint32_t a;
    asm("{ .reg .u64 t; cvta.to.shared.u64 t, %1; cvt.u32.u64 %0, t; }"
        : "=r"(a) : "l"(p));
    return a;
}

#define MBARRIER_INIT(mbar, cnt) \
    asm volatile("mbarrier.init.shared.b64 [%0], %1;" \
                 :: "r"((uint32_t)(mbar)), "r"((uint32_t)(cnt)) : "memory")
#define MBARRIER_EXPECT_TX(mbar, tx) \
    asm volatile("mbarrier.arrive.expect_tx.shared.b64 _, [%0], %1;" \
                 :: "r"((uint32_t)(mbar)), "r"((uint32_t)(tx)) : "memory")
#define MBARRIER_ARRIVE(mbar) \
    asm volatile("mbarrier.arrive.shared.b64 _, [%0];" \
                 :: "r"((uint32_t)(mbar)) : "memory")

#define MBARRIER_WAIT_PARITY(mbar, par) do {                                   \
    uint32_t _m = (uint32_t)(mbar);                                            \
    uint32_t _p = (uint32_t)(par);                                             \
    uint32_t _done;                                                            \
    asm volatile("{\n\t.reg .pred p;\n\t"                                      \
        "mbarrier.try_wait.parity.shared.b64 p, [%1], %2;\n\t"                 \
        "selp.b32 %0, 1, 0, p;\n\t}"                                           \
        : "=r"(_done) : "r"(_m), "r"(_p) : "memory");                          \
    if (!_done) {                                                              \
        asm volatile("{\n\t.reg .pred P1;\n\t"                                 \
            "WL_%=:\n\t"                                                       \
            "mbarrier.try_wait.parity.shared.b64 P1, [%0], %1;\n\t"            \
            "@P1 bra.uni WD_%=;\n\t"                                           \
            "bra.uni WL_%=;\n\t"                                               \
            "WD_%=:\n\t}"                                                      \
            :: "r"(_m), "r"(_p) : "memory");                                   \
    }                                                                          \
} while (0)

#define CP_BULK(dst, src, nbytes, mbar) \
    asm volatile( \
        "cp.async.bulk.shared::cluster.global.mbarrier::complete_tx::bytes " \
        "[%0], [%1], %2, [%3];" \
        :: "r"((uint32_t)(dst)), "l"(src), "r"((uint32_t)(nbytes)), \
           "r"((uint32_t)(mbar)) : "memory")

__device__ __forceinline__ void imma(int* d, const uint32_t* a,
                                     const uint32_t* b) {
    asm volatile(
        "mma.sync.aligned.m16n8k32.row.col.s32.s8.s8.s32 "
        "{%0,%1,%2,%3},{%4,%5,%6,%7},{%8,%9},{%0,%1,%2,%3};"
        : "+r"(d[0]), "+r"(d[1]), "+r"(d[2]), "+r"(d[3])
        : "r"(a[0]), "r"(a[1]), "r"(a[2]), "r"(a[3]),
          "r"(b[0]), "r"(b[1]));
}

__device__ __forceinline__ int dp4a_(int a, int b, int c) {
    int d;
    asm("dp4a.s32.s32 %0, %1, %2, %3;" : "=r"(d) : "r"(a), "r"(b), "r"(c));
    return d;
}

// -------------------- weight convert: int32 [E][k][n] -> frag + swz --------
__global__ void convw_kernel(const int* __restrict__ W,
                             int8_t* __restrict__ Ofrag,
                             int8_t* __restrict__ Oswz) {
    __shared__ int8_t tile[32][33];
    const int e  = blockIdx.z;
    const int n0 = blockIdx.x * 32;
    const int k0 = blockIdx.y * 32;
    const int tx = threadIdx.x, ty = threadIdx.y;

    const int* src = W + ((size_t)e * HH + k0) * HH + n0;
#pragma unroll
    for (int r = 0; r < 4; r++) {
        tile[ty + r * 8][tx] = (int8_t)src[(size_t)(ty + r * 8) * HH + tx];
    }
    __syncthreads();
    const int t  = ty * 32 + tx;
    const int nr = t >> 3;              // 0..31 (n within block)
    const int c4 = (t & 7) * 4;         // 0..28 (k within block)
    uint32_t p = (uint32_t)(uint8_t)tile[c4 + 0][nr]
               | ((uint32_t)(uint8_t)tile[c4 + 1][nr] << 8)
               | ((uint32_t)(uint8_t)tile[c4 + 2][nr] << 16)
               | ((uint32_t)(uint8_t)tile[c4 + 3][nr] << 24);
    const int ng   = n0 + nr;
    const int nb   = ng >> 6;
    const int rowT = ng & 63;
    const int kb   = k0 >> 7;
    const int kin  = (k0 & 127) + c4;
    const size_t tbase = (((size_t)(e * 32 + nb) * 16 + kb) << 13);
    // chunk-swizzled row layout (for dp4a)
    const int ch = kin >> 4;
    const uint32_t sw = (uint32_t)(((ch ^ (rowT & 7)) & 7) << 4) + (kin & 15);
    *(uint32_t*)(Oswz + tbase + rowT * 128 + sw) = p;
    // fragment order (for IMMA)
    const int nblk = rowT >> 3, grp = rowT & 7;
    const int ks = kin >> 5, c = (kin >> 4) & 1, tg = (kin >> 2) & 3;
    *(uint32_t*)(Ofrag + tbase + (nblk * 4 + ks) * 256
                 + (grp * 4 + tg) * 8 + c * 4) = p;
}

// -------------------- activation quantize: hi frag + lo swz ---------------
__global__ void quant_kernel(const float* __restrict__ X,
                             int8_t* __restrict__ Qh,
                             int8_t* __restrict__ Ql,
                             float* __restrict__ RS) {
    const int row = blockIdx.x;          // 0 .. EE*TT-1
    const float* x = X + (size_t)row * HH;
    const int t = threadIdx.x;           // 0..127

    float4 v[4];
#pragma unroll
    for (int j = 0; j < 4; j++) v[j] = ((const float4*)x)[t * 4 + j];

    float m = 0.0f;
#pragma unroll
    for (int j = 0; j < 4; j++) {
        m = fmaxf(m, fabsf(v[j].x)); m = fmaxf(m, fabsf(v[j].y));
        m = fmaxf(m, fabsf(v[j].z)); m = fmaxf(m, fabsf(v[j].w));
    }
#pragma unroll
    for (int o = 16; o; o >>= 1)
        m = fmaxf(m, __shfl_xor_sync(0xFFFFFFFFu, m, o));
    __shared__ float wr[4];
    if ((t & 31) == 0) wr[t >> 5] = m;
    __syncthreads();
    float mx = fmaxf(fmaxf(wr[0], wr[1]), fmaxf(wr[2], wr[3]));
    mx = fmaxf(mx, 1e-20f);
    const float inv = 32600.0f / mx;

    uint32_t hw[4], lw[4];
#pragma unroll
    for (int j = 0; j < 4; j++) {
        const int q0 = __float2int_rn(v[j].x * inv);
        const int q1 = __float2int_rn(v[j].y * inv);
        const int q2 = __float2int_rn(v[j].z * inv);
        const int q3 = __float2int_rn(v[j].w * inv);
        const int h0 = (q0 + 128) >> 8, h1 = (q1 + 128) >> 8;
        const int h2 = (q2 + 128) >> 8, h3 = (q3 + 128) >> 8;
        const int l0 = q0 - (h0 << 8), l1 = q1 - (h1 << 8);
        const int l2 = q2 - (h2 << 8), l3 = q3 - (h3 << 8);
        hw[j] = (h0 & 255) | ((h1 & 255) << 8) | ((h2 & 255) << 16)
              | ((uint32_t)(h3 & 255) << 24);
        lw[j] = (l0 & 255) | ((l1 & 255) << 8) | ((l2 & 255) << 16)
              | ((uint32_t)(l3 & 255) << 24);
    }

    const int e   = row >> 12;
    const int mm  = row & 4095;
    const int mb  = mm >> 7;
    const int r   = mm & 127;
    const int kb  = t >> 3;              // 0..15
    const int sub = t & 7;               // chunk index
    const size_t tbase = (((size_t)(e * 32 + mb) * 16 + kb) << 14);

    // lo: chunk-swizzled 16B store
    const uint32_t sw = (uint32_t)(((sub ^ (r & 7)) & 7) << 4);
    *(int4*)(Ql + tbase + r * 128 + sw) =
        make_int4(lw[0], lw[1], lw[2], lw[3]);

    // hi: fragment-order 4B stores
    const int wm = r >> 6, mt = (r >> 4) & 3, h = (r >> 3) & 1, grp = r & 7;
    const int ks = sub >> 1, c = sub & 1;
    const size_t hb = tbase + wm * 8192 + (mt * 4 + ks) * 512;
#pragma unroll
    for (int j = 0; j < 4; j++) {
        *(uint32_t*)(Qh + hb + (grp * 4 + j) * 16 + (c * 2 + h) * 4) = hw[j];
    }
    if (t == 0) RS[row] = mx / 32600.0f;
}

// -------------------- decoupled hybrid GEMM --------------------------------
__global__ void __launch_bounds__(256, 2)
imma_gemm(const int8_t* __restrict__ Ahf, const int8_t* __restrict__ Als,
          const float* __restrict__ rs,
          const int8_t* __restrict__ Bf, const int8_t* __restrict__ Bs,
          const float* __restrict__ cs, float* __restrict__ C) {
    extern __shared__ __align__(128) char sm[];
    __shared__ __align__(8) uint64_t mbar_s[2 * NSTAGE];
    const uint32_t sbase = smem_u32(sm);
    const uint32_t mbF = smem_u32(mbar_s);
    const uint32_t mbE = mbF + 8 * NSTAGE;
    const int tid = threadIdx.x;
    const int lane = tid & 31, wid = tid >> 5;

    const int e  = blockIdx.z;
    const int mb = blockIdx.y;           // 0..31
    const int nb = blockIdx.x;           // 0..31

    const int8_t* hiB = Ahf + (((size_t)(e * 32 + mb) * 16) << 14);
    const int8_t* loB = Als + (((size_t)(e * 32 + mb) * 16) << 14);
    const int8_t* bfB = Bf  + (((size_t)(e * 32 + nb) * 16) << 13);
    const int8_t* bsB = Bs  + (((size_t)(e * 32 + nb) * 16) << 13);

    // ---- mma-warp config (wid 0..3): frag-order loads ----
    const int grp = lane >> 2;
    const int wm = wid >> 1;             // 0..1 -> 64 rows
    const int wn = wid & 1;              // 0..1 -> 32 cols
    const uint32_t aBase = (uint32_t)(wm * 8192 + lane * 16);
    const uint32_t bBase = (uint32_t)(OFF_BF + wn * 4096 + lane * 8);

    // ---- dp4a-warp config (wid 4..7): chunk-swizzled loads ----
    const int wtr = wid - 4;             // 0..3 -> rows wtr*32
    const int lg = lane & 3;
    const int lh = lane >> 2;
    const uint32_t dpA0 = (uint32_t)(OFF_ALO + (wtr * 32 + lg) * 128);
    const uint32_t dpB0 = (uint32_t)(OFF_BS + lh * 128);

    int acc_h[4][4][4];
    int acc_lo[8][8];
    if (wid < 4) {
#pragma unroll
        for (int a = 0; a < 4; a++)
#pragma unroll
            for (int b = 0; b < 4; b++)
#pragma unroll
                for (int c = 0; c < 4; c++) acc_h[a][b][c] = 0;
    } else {
#pragma unroll
        for (int a = 0; a < 8; a++)
#pragma unroll
            for (int b = 0; b < 8; b++) acc_lo[a][b] = 0;
    }

    if (tid == 0) {
#pragma unroll
        for (int s = 0; s < NSTAGE; s++) {
            MBARRIER_INIT(mbF + 8 * s, 1);
            MBARRIER_INIT(mbE + 8 * s, 256);
        }
    }
    __syncthreads();

    if (tid == 0) {
#pragma unroll
        for (int p = 0; p < NSTAGE; p++) {
            const uint32_t st = sbase + p * STAGE;
            MBARRIER_EXPECT_TX(mbF + 8 * p, STAGE);
            CP_BULK(st,           hiB + ((size_t)p << 14), 16384, mbF + 8 * p);
            CP_BULK(st + OFF_ALO, loB + ((size_t)p << 14), 16384, mbF + 8 * p);
            CP_BULK(st + OFF_BF,  bfB + ((size_t)p << 13),  8192, mbF + 8 * p);
            CP_BULK(st + OFF_BS,  bsB + ((size_t)p << 13),  8192, mbF + 8 * p);
        }
    }

#pragma unroll 1
    for (int i = 0; i < NKIT; i++) {
        const int s = i & 1;
        const int ph = (i >> 1) & 1;
        MBARRIER_WAIT_PARITY(mbF + 8 * s, ph);

        const char* st = sm + s * STAGE;

        if (wid < 4) {
            // ============ IMMA warps: fragment-order wide LDS ============
#pragma unroll
            for (int ks = 0; ks < 4; ks++) {
                int4 af[4];
#pragma unroll
                for (int mt = 0; mt < 4; mt++)
                    af[mt] = *(const int4*)(st + aBase
                                            + (mt * 4 + ks) * 512);
                int2 bfr[4];
#pragma unroll
                for (int nt = 0; nt < 4; nt++)
                    bfr[nt] = *(const int2*)(st + bBase
                                             + (nt * 4 + ks) * 256);
#pragma unroll
                for (int mt = 0; mt < 4; mt++)
#pragma unroll
                    for (int nt = 0; nt < 4; nt++)
                        imma(acc_h[mt][nt], (const uint32_t*)&af[mt],
                             (const uint32_t*)&bfr[nt]);
            }
        } else {
            // ============ dp4a warps: chunk-swizzled loads ============
#pragma unroll 2
            for (int kb = 0; kb < 128; kb += 16) {
                const uint32_t cA0 =
                    (uint32_t)(((((kb >> 4)) ^ lg) & 7) << 4);
                const uint32_t cA1 = cA0 ^ 64u;
                const uint32_t cB =
                    (uint32_t)(((((kb >> 4)) ^ lh) & 7) << 4);
                int4 bv[8];
#pragma unroll
                for (int j2 = 0; j2 < 8; j2++) {
                    bv[j2] = *(const int4*)(st + dpB0
                                            + (uint32_t)(j2 * 1024) + cB);
                }
#pragma unroll
                for (int j = 0; j < 8; j++) {
                    const int4 a = *(const int4*)(st + dpA0
                                     + (uint32_t)(j * 512)
                                     + ((j & 1) ? cA1 : cA0));
#pragma unroll
                    for (int j2 = 0; j2 < 8; j2++) {
                        acc_lo[j][j2] =
                            dp4a_(a.x, bv[j2].x,
                            dp4a_(a.y, bv[j2].y,
                            dp4a_(a.z, bv[j2].z,
                            dp4a_(a.w, bv[j2].w, acc_lo[j][j2]))));
                    }
                }
            }
        }

        MBARRIER_ARRIVE(mbE + 8 * s);

        if (tid == 0 && i + NSTAGE < NKIT) {
            MBARRIER_WAIT_PARITY(mbE + 8 * s, ph);
            const int kn = i + NSTAGE;
            const uint32_t stw = sbase + s * STAGE;
            MBARRIER_EXPECT_TX(mbF + 8 * s, STAGE);
            CP_BULK(stw,           hiB + ((size_t)kn << 14), 16384, mbF + 8 * s);
            CP_BULK(stw + OFF_ALO, loB + ((size_t)kn << 14), 16384, mbF + 8 * s);
            CP_BULK(stw + OFF_BF,  bfB + ((size_t)kn << 13),  8192, mbF + 8 * s);
            CP_BULK(stw + OFF_BS,  bsB + ((size_t)kn << 13),  8192, mbF + 8 * s);
        }
    }

    // ---------------- epilogue ----------------
    __syncthreads();

    int* xch = (int*)sm;                // 128 x XPITCH int32 (34.8KB)
    if (wid >= 4) {
#pragma unroll
        for (int j = 0; j < 8; j++)
#pragma unroll
            for (int j2 = 0; j2 < 8; j2++) {
                const int r = wtr * 32 + lg + 4 * j;
                const int c = lh + 8 * j2;
                xch[r * XPITCH + c] = acc_lo[j][j2];
            }
    }
    __syncthreads();

    if (wid < 4) {
        const float* rsp = rs + (size_t)e * TT + mb * BM;
        const float* csp = cs + (size_t)e * HH + nb * BN;
        float* Cg = C + ((size_t)e * TT + mb * BM) * HH + nb * BN;

#pragma unroll
        for (int mt = 0; mt < 4; mt++) {
            const int rA = wm * 64 + mt * 16 + grp;
            const float sr0 = rsp[rA];
            const float sr1 = rsp[rA + 8];
#pragma unroll
            for (int nt = 0; nt < 4; nt++) {
                const int cn = wn * 32 + nt * 8 + (lane & 3) * 2;
                const float sc0 = csp[cn];
                const float sc1 = csp[cn + 1];
                const int* hh = acc_h[mt][nt];
                const int2 l0 = *(const int2*)(xch + rA * XPITCH + cn);
                const int2 l1 = *(const int2*)(xch + (rA + 8) * XPITCH + cn);
                float2 r0, r1;
                r0.x = fmaf(256.0f, (float)hh[0], (float)l0.x) * (sr0 * sc0);
                r0.y = fmaf(256.0f, (float)hh[1], (float)l0.y) * (sr0 * sc1);
                r1.x = fmaf(256.0f, (float)hh[2], (float)l1.x) * (sr1 * sc0);
                r1.y = fmaf(256.0f, (float)hh[3], (float)l1.y) * (sr1 * sc1);
                *(float2*)(Cg + (size_t)rA * HH + cn)       = r0;
                *(float2*)(Cg + (size_t)(rA + 8) * HH + cn) = r1;
            }
        }
    }
}

// -------------------- launcher --------------------------------------------
extern "C" void kernel_launch(void* const* d_in, const int* in_sizes, int n_in,
                              void* d_out, int out_size) {
    const float* x   = (const float*)d_in[0];
    const int*   w1q = (const int*)d_in[1];
    const float* w1s = (const float*)d_in[2];
    const int*   w2q = (const int*)d_in[3];
    const float* w2s = (const float*)d_in[4];
    float*       out = (float*)d_out;

    void *pw1f, *pw1sw, *pw2f, *pw2sw, *pahf, *pals, *prs, *ph;
    cudaGetSymbolAddress(&pw1f,  g_w1f);
    cudaGetSymbolAddress(&pw1sw, g_w1s);
    cudaGetSymbolAddress(&pw2f,  g_w2f);
    cudaGetSymbolAddress(&pw2sw, g_w2s);
    cudaGetSymbolAddress(&pahf,  g_ahf);
    cudaGetSymbolAddress(&pals,  g_als);
    cudaGetSymbolAddress(&prs,   g_rs);
    cudaGetSymbolAddress(&ph,    g_h);

    dim3 cb(32, 8), cg(HH / 32, HH / 32, EE);
    convw_kernel<<<cg, cb>>>(w1q, (int8_t*)pw1f, (int8_t*)pw1sw);
    convw_kernel<<<cg, cb>>>(w2q, (int8_t*)pw2f, (int8_t*)pw2sw);

    quant_kernel<<<EE * TT, 128>>>(x, (int8_t*)pahf, (int8_t*)pals,
                                   (float*)prs);

    cudaFuncSetAttribute(imma_gemm,
                         cudaFuncAttributeMaxDynamicSharedMemorySize, DYNSMEM);
    dim3 gg(HH / BN, TT / BM, EE);   // (32, 32, 8)

    imma_gemm<<<gg, 256, DYNSMEM>>>((const int8_t*)pahf, (const int8_t*)pals,
                                    (const float*)prs, (const int8_t*)pw1f,
                                    (const int8_t*)pw1sw, w1s, (float*)ph);

    quant_kernel<<<EE * TT, 128>>>((const float*)ph, (int8_t*)pahf,
                                   (int8_t*)pals, (float*)prs);

    imma_gemm<<<gg, 256, DYNSMEM>>>((const int8_t*)pahf, (const int8_t*)pals,
                                    (const float*)prs, (const int8_t*)pw2f,
                                    (const int8_t*)pw2sw, w2s, out);
}